// round 9
// baseline (speedup 1.0000x reference)
#include <cuda_runtime.h>
#include <cstdint>
#include <float.h>

#define NROWS  2048
#define VV     50257
#define EE     64
#define KSEL   250
#define NT     256
#define BUFCAP 512
#define CH     4
#define SLOT   512
#define NB     1024
#define T0     2.45f

__device__ unsigned long long g_cand[(size_t)NROWS * CH * SLOT];  // 33.5 MB scratch
__device__ int                g_cnt[NROWS * CH];
__device__ int                g_done[NROWS];                       // zero-init, self-resetting

__device__ __forceinline__ unsigned long long make_comp(float x, unsigned gidx) {
    unsigned ub  = __float_as_uint(x);
    unsigned key = (ub & 0x80000000u) ? ~ub : (ub | 0x80000000u);
    return ((unsigned long long)key << 32) | (unsigned)(~gidx);
}

__global__ void __launch_bounds__(NT, 6) fused_kernel(
    const float* __restrict__ gx, const float* __restrict__ cb,
    const float* __restrict__ W,  const float* __restrict__ logits,
    float* __restrict__ out)
{
    __shared__ unsigned long long buf[BUFCAP];
    __shared__ unsigned long long bkt[BUFCAP];
    __shared__ int   hist[NB];
    __shared__ int   preA[NB];
    __shared__ float su[EE];
    __shared__ float red[16];
    __shared__ int   wsum[8];
    __shared__ int   woff[8];
    __shared__ unsigned skmin, skmax;
    __shared__ int   scnt;
    __shared__ int   icnt[4];
    __shared__ float fctl[4];   // [0]=lo [1]=hi [2]=Tsel [3]=c0
    __shared__ int   ictl[2];
    __shared__ int   soff[CH + 1];
    __shared__ int   sbad;
    __shared__ int   slast;

    const int tid   = threadIdx.x;
    const int lane  = tid & 31;
    const int wid   = tid >> 5;
    const int chunk = blockIdx.x;
    const int row   = blockIdx.y;
    const float* __restrict__ lrow = logits + (size_t)row * VV;

    if (tid == 0) scnt = 0;
    __syncthreads();

    // ================== phase 1: stream this CTA's quarter-row ==================
    uintptr_t a = (uintptr_t)lrow;
    const int lead  = (int)(((16u - (unsigned)(a & 15u)) & 15u) >> 2);
    const int nv4   = (VV - lead) >> 2;
    const int tail0 = lead + nv4 * 4;
    const float4* __restrict__ l4 = reinterpret_cast<const float4*>(lrow + lead);
    unsigned long long* __restrict__ slot = g_cand + ((size_t)(row * CH + chunk)) * SLOT;

    const int c4 = (nv4 + CH - 1) / CH;
    const int b4 = chunk * c4;
    const int e4 = min(b4 + c4, nv4);

    if (chunk == 0) {
        for (int i = tid; i < lead; i += NT) {
            float x = __ldcs(&lrow[i]);
            if (x >= T0) {
                int p = atomicAdd(&scnt, 1);
                if (p < SLOT) slot[p] = make_comp(x, (unsigned)i);
            }
        }
    }
    if (chunk == CH - 1) {
        for (int i = tail0 + tid; i < VV; i += NT) {
            float x = __ldcs(&lrow[i]);
            if (x >= T0) {
                int p = atomicAdd(&scnt, 1);
                if (p < SLOT) slot[p] = make_comp(x, (unsigned)i);
            }
        }
    }
    #pragma unroll 8
    for (int i = b4 + tid; i < e4; i += NT) {
        float4 x = __ldcs(&l4[i]);
        unsigned pr = (x.x >= T0 ? 1u : 0u) | (x.y >= T0 ? 2u : 0u)
                    | (x.z >= T0 ? 4u : 0u) | (x.w >= T0 ? 8u : 0u);
        if (pr) {
            int base = atomicAdd(&scnt, __popc(pr));
            float vals[4] = { x.x, x.y, x.z, x.w };
            unsigned g0 = (unsigned)(lead + 4 * i);
            #pragma unroll
            for (int c = 0; c < 4; ++c) {
                if (pr & (1u << c)) {
                    if (base < SLOT) slot[base] = make_comp(vals[c], g0 + c);
                    ++base;
                }
            }
        }
    }
    __syncthreads();
    if (tid == 0) g_cnt[row * CH + chunk] = scnt;
    __threadfence();             // release: slot + g_cnt visible before ticket
    __syncthreads();
    if (tid == 0) {
        int old = atomicAdd(&g_done[row], 1);
        slast = (old == CH - 1);
    }
    __syncthreads();
    if (!slast) return;
    __threadfence();             // acquire: other CTAs' slot/g_cnt now visible
    if (tid == 0) g_done[row] = 0;   // reset for next launch/replay

    // ================== phase 2: selector (one CTA per row) ==================
    // u vector + c0 partials
    if (tid < EE) {
        float g = gx[row * EE + tid], c = cb[row * EE + tid];
        su[tid] = -0.5f * g + 20.0f * c;
        float p = 0.5f * g * c - 10.0f * c * c;
        #pragma unroll
        for (int o = 16; o; o >>= 1) p += __shfl_xor_sync(0xffffffffu, p, o);
        if (lane == 0) red[wid] = p;
    }
    if (tid == 0) {
        int off = 0;
        bool bad = false;
        #pragma unroll
        for (int j = 0; j < CH; ++j) {
            soff[j] = off;
            int c = g_cnt[row * CH + j];
            if (c > SLOT) bad = true;
            off += c;
        }
        soff[CH] = off;
        sbad = (bad || off < KSEL || off > BUFCAP) ? 1 : 0;
        skmin = 0xffffffffu; skmax = 0u;
    }
    for (int i = tid; i < NB; i += NT) hist[i] = 0;
    __syncthreads();
    if (tid == 0) fctl[3] = red[0] + red[1];   // c0
    int C;

    if (!sbad) {
        C = soff[CH];
        #pragma unroll
        for (int j = 0; j < CH; ++j) {
            const unsigned long long* __restrict__ sl =
                g_cand + ((size_t)(row * CH + j)) * SLOT;
            int n = soff[j + 1] - soff[j];
            for (int i = tid; i < n; i += NT) buf[soff[j] + i] = sl[i];
        }
    } else {
        // ---------- exact adaptive fallback (rare, non-Gaussian inputs) ----------
        float mx = -FLT_MAX, mn = FLT_MAX;
        for (int i = tid; i < VV; i += NT) {
            float x = lrow[i];
            mx = fmaxf(mx, x); mn = fminf(mn, x);
        }
        #pragma unroll
        for (int o = 16; o; o >>= 1) {
            mx = fmaxf(mx, __shfl_xor_sync(0xffffffffu, mx, o));
            mn = fminf(mn, __shfl_xor_sync(0xffffffffu, mn, o));
        }
        if (lane == 0) { red[wid] = mx; red[8 + wid] = mn; }
        __syncthreads();
        if (tid == 0) {
            float M = -FLT_MAX, m = FLT_MAX;
            for (int w = 0; w < 8; ++w) {
                M = fmaxf(M, red[w]); m = fminf(m, red[8 + w]);
            }
            fctl[0] = m; fctl[1] = M; ictl[1] = VV;
            ictl[0] = 0;
            icnt[0] = icnt[1] = icnt[2] = icnt[3] = 0;
        }
        __syncthreads();
        for (int it = 0; it < 30; ++it) {
            if (ictl[0]) break;
            float lo = fctl[0], hi = fctl[1];
            float step = (hi - lo) * 0.2f;
            float t0 = lo + step, t1 = lo + 2.f*step, t2 = lo + 3.f*step, t3 = lo + 4.f*step;
            int c0 = 0, c1 = 0, c2 = 0, c3 = 0;
            for (int i = tid; i < VV; i += NT) {
                float x = lrow[i];
                c0 += (x >= t0); c1 += (x >= t1); c2 += (x >= t2); c3 += (x >= t3);
            }
            #pragma unroll
            for (int o = 16; o; o >>= 1) {
                c0 += __shfl_xor_sync(0xffffffffu, c0, o);
                c1 += __shfl_xor_sync(0xffffffffu, c1, o);
                c2 += __shfl_xor_sync(0xffffffffu, c2, o);
                c3 += __shfl_xor_sync(0xffffffffu, c3, o);
            }
            if (lane == 0) {
                atomicAdd(&icnt[0], c0); atomicAdd(&icnt[1], c1);
                atomicAdd(&icnt[2], c2); atomicAdd(&icnt[3], c3);
            }
            __syncthreads();
            if (tid == 0) {
                int   n[5]  = { ictl[1], icnt[0], icnt[1], icnt[2], icnt[3] };
                float tt[5] = { lo, t0, t1, t2, t3 };
                int j = 0;
                for (int q = 1; q < 5; ++q) if (n[q] >= KSEL) j = q;
                bool degen = !(t0 > lo && t3 < hi);
                if (n[j] <= BUFCAP || degen || it == 29) {
                    fctl[2] = tt[j]; ictl[0] = 1;
                } else {
                    fctl[0] = tt[j]; ictl[1] = n[j];
                    fctl[1] = (j < 4) ? tt[j + 1] : hi;
                }
                icnt[0] = icnt[1] = icnt[2] = icnt[3] = 0;
            }
            __syncthreads();
        }
        float T = fctl[2];
        if (tid == 0) scnt = 0;
        __syncthreads();
        for (int i = tid; i < VV; i += NT) {
            float x = lrow[i];
            if (x >= T) {
                int p = atomicAdd(&scnt, 1);
                if (p < BUFCAP) buf[p] = make_comp(x, (unsigned)i);
            }
        }
        __syncthreads();
        C = min(scnt, BUFCAP);
    }
    __syncthreads();

    // ------------- counting-sort ranking -------------
    unsigned long long m0 = (tid      < C) ? buf[tid]      : 0ull;
    unsigned long long m1 = (tid + NT < C) ? buf[tid + NT] : 0ull;
    const unsigned k0 = (unsigned)(m0 >> 32);
    const unsigned k1 = (unsigned)(m1 >> 32);

    {
        unsigned kmn = 0xffffffffu, kmx = 0u;
        if (tid      < C) { kmn = min(kmn, k0); kmx = max(kmx, k0); }
        if (tid + NT < C) { kmn = min(kmn, k1); kmx = max(kmx, k1); }
        #pragma unroll
        for (int o = 16; o; o >>= 1) {
            kmn = min(kmn, __shfl_xor_sync(0xffffffffu, kmn, o));
            kmx = max(kmx, __shfl_xor_sync(0xffffffffu, kmx, o));
        }
        if (lane == 0) { atomicMin(&skmin, kmn); atomicMax(&skmax, kmx); }
    }
    __syncthreads();
    const unsigned kminv = skmin;
    const unsigned long long spanp1 = (unsigned long long)(skmax - skmin) + 1ull;

    int b0 = -1, b1 = -1;
    if (tid      < C) b0 = (int)(((unsigned long long)(k0 - kminv) * NB) / spanp1);
    if (tid + NT < C) b1 = (int)(((unsigned long long)(k1 - kminv) * NB) / spanp1);
    if (b0 >= 0) atomicAdd(&hist[b0], 1);
    if (b1 >= 0) atomicAdd(&hist[b1], 1);
    __syncthreads();

    // exclusive ascending scan of hist[NB] -> preA[NB], 4 bins/thread
    {
        const int bq = tid * 4;
        int h0 = hist[bq], h1 = hist[bq+1], h2 = hist[bq+2], h3 = hist[bq+3];
        int s = h0 + h1 + h2 + h3;
        int incl = s;
        #pragma unroll
        for (int o = 1; o < 32; o <<= 1) {
            int n = __shfl_up_sync(0xffffffffu, incl, o);
            if (lane >= o) incl += n;
        }
        if (lane == 31) wsum[wid] = incl;
        __syncthreads();
        if (wid == 0) {
            int w = (lane < 8) ? wsum[lane] : 0;
            int wi = w;
            #pragma unroll
            for (int o = 1; o < 8; o <<= 1) {
                int n = __shfl_up_sync(0xffffffffu, wi, o);
                if (lane >= o) wi += n;
            }
            if (lane < 8) woff[lane] = wi - w;
        }
        __syncthreads();
        int run = incl - s + woff[wid];
        preA[bq]     = run;            run += h0;
        preA[bq + 1] = run;            run += h1;
        preA[bq + 2] = run;            run += h2;
        preA[bq + 3] = run;
    }
    __syncthreads();

    int st0 = 0, ln0 = 0, st1 = 0, ln1 = 0;
    if (b0 >= 0) { st0 = preA[b0]; ln0 = hist[b0]; }
    if (b1 >= 0) { st1 = preA[b1]; ln1 = hist[b1]; }
    __syncthreads();
    if (b0 >= 0) { int p = atomicAdd(&preA[b0], 1); bkt[p] = m0; }
    if (b1 >= 0) { int p = atomicAdd(&preA[b1], 1); bkt[p] = m1; }
    __syncthreads();

    int r0 = 0, r1 = 0;
    if (b0 >= 0) {
        r0 = C - (st0 + ln0);
        for (int j = st0; j < st0 + ln0; ++j) r0 += (bkt[j] > m0);
    }
    if (b1 >= 0) {
        r1 = C - (st1 + ln1);
        for (int j = st1; j < st1 + ln1; ++j) r1 += (bkt[j] > m1);
    }

    // ------------- fused dot + direct scatter -------------
    const float c0v = fctl[3];
    const float4* __restrict__ u4 = reinterpret_cast<const float4*>(su);
    #pragma unroll
    for (int s = 0; s < 2; ++s) {
        int b = s ? b1 : b0;
        int r = s ? r1 : r0;
        unsigned long long mine = s ? m1 : m0;
        if (b >= 0 && r < KSEL) {
            unsigned idx = ~((unsigned)(mine & 0xffffffffull));
            const float4* __restrict__ wr =
                reinterpret_cast<const float4*>(W + (size_t)idx * EE);
            float acc = 0.f, wsq = 0.f;
            #pragma unroll
            for (int q = 0; q < EE / 4; ++q) {
                float4 w = wr[q], u = u4[q];
                acc += w.x * u.x + w.y * u.y + w.z * u.z + w.w * u.w;
                wsq += w.x * w.x + w.y * w.y + w.z * w.z + w.w * w.w;
            }
            size_t o = (size_t)row * KSEL + (size_t)r;
            out[o] = acc - 10.0f * wsq + c0v;
            out[(size_t)NROWS * KSEL + o] = (float)idx;
        }
    }
}

extern "C" void kernel_launch(void* const* d_in, const int* in_sizes, int n_in,
                              void* d_out, int out_size)
{
    (void)in_sizes; (void)n_in; (void)out_size;
    fused_kernel<<<dim3(CH, NROWS), NT>>>(
        (const float*)d_in[0], (const float*)d_in[1],
        (const float*)d_in[2], (const float*)d_in[3], (float*)d_out);
}

// round 10
// speedup vs baseline: 1.1558x; 1.1558x over previous
#include <cuda_runtime.h>
#include <cstdint>
#include <float.h>

#define NROWS  2048
#define VV     50257
#define EE     64
#define KSEL   250
#define NT     256
#define BUFCAP 512
#define CH     4
#define SLOT   512
#define NB     512
#define T0     2.45f

__device__ unsigned long long g_cand[(size_t)NROWS * CH * SLOT];  // 33.5 MB scratch
__device__ int                g_cnt[NROWS * CH];
__device__ int                g_done[NROWS];                       // zero-init, self-resetting

__device__ __forceinline__ unsigned long long make_comp(float x, unsigned gidx) {
    unsigned ub  = __float_as_uint(x);
    unsigned key = (ub & 0x80000000u) ? ~ub : (ub | 0x80000000u);
    return ((unsigned long long)key << 32) | (unsigned)(~gidx);
}

// ---------------------------------------------------------------------------
// Phase 2 selector: __noinline__ so its register/spill pressure cannot leak
// into the streaming loop's allocation. Runs once per row (last-arriving CTA).
// ---------------------------------------------------------------------------
__device__ __noinline__ void selector(
    int row,
    const float* __restrict__ gx, const float* __restrict__ cb,
    const float* __restrict__ W,  const float* __restrict__ logits,
    float* __restrict__ out)
{
    __shared__ unsigned long long buf[BUFCAP];
    __shared__ unsigned long long bkt[BUFCAP];
    __shared__ int   hist[NB];
    __shared__ int   preA[NB];
    __shared__ float su[EE];
    __shared__ float red[16];
    __shared__ int   wsum[8];
    __shared__ int   woff[8];
    __shared__ unsigned skmin, skmax;
    __shared__ int   qcnt;
    __shared__ int   icnt[4];
    __shared__ float fctl[4];   // [0]=lo [1]=hi [2]=Tsel [3]=c0
    __shared__ int   ictl[2];
    __shared__ int   soff[CH + 1];
    __shared__ int   sbad;

    const int tid  = threadIdx.x;
    const int lane = tid & 31;
    const int wid  = tid >> 5;
    const float* __restrict__ lrow = logits + (size_t)row * VV;

    // u vector + c0 partials
    if (tid < EE) {
        float g = gx[row * EE + tid], c = cb[row * EE + tid];
        su[tid] = -0.5f * g + 20.0f * c;
        float p = 0.5f * g * c - 10.0f * c * c;
        #pragma unroll
        for (int o = 16; o; o >>= 1) p += __shfl_xor_sync(0xffffffffu, p, o);
        if (lane == 0) red[wid] = p;
    }
    if (tid == 0) {
        int off = 0;
        bool bad = false;
        #pragma unroll
        for (int j = 0; j < CH; ++j) {
            soff[j] = off;
            int c = g_cnt[row * CH + j];
            if (c > SLOT) bad = true;
            off += c;
        }
        soff[CH] = off;
        sbad = (bad || off < KSEL || off > BUFCAP) ? 1 : 0;
        skmin = 0xffffffffu; skmax = 0u;
    }
    for (int i = tid; i < NB; i += NT) hist[i] = 0;
    __syncthreads();
    if (tid == 0) fctl[3] = red[0] + red[1];   // c0
    int C;

    if (!sbad) {
        C = soff[CH];
        #pragma unroll
        for (int j = 0; j < CH; ++j) {
            const unsigned long long* __restrict__ sl =
                g_cand + ((size_t)(row * CH + j)) * SLOT;
            int n = soff[j + 1] - soff[j];
            for (int i = tid; i < n; i += NT) buf[soff[j] + i] = sl[i];
        }
    } else {
        // ---------- exact adaptive fallback (rare, non-Gaussian inputs) ----------
        float mx = -FLT_MAX, mn = FLT_MAX;
        for (int i = tid; i < VV; i += NT) {
            float x = lrow[i];
            mx = fmaxf(mx, x); mn = fminf(mn, x);
        }
        #pragma unroll
        for (int o = 16; o; o >>= 1) {
            mx = fmaxf(mx, __shfl_xor_sync(0xffffffffu, mx, o));
            mn = fminf(mn, __shfl_xor_sync(0xffffffffu, mn, o));
        }
        if (lane == 0) { red[wid] = mx; red[8 + wid] = mn; }
        __syncthreads();
        if (tid == 0) {
            float M = -FLT_MAX, m = FLT_MAX;
            for (int w = 0; w < 8; ++w) {
                M = fmaxf(M, red[w]); m = fminf(m, red[8 + w]);
            }
            fctl[0] = m; fctl[1] = M; ictl[1] = VV;
            ictl[0] = 0;
            icnt[0] = icnt[1] = icnt[2] = icnt[3] = 0;
        }
        __syncthreads();
        for (int it = 0; it < 30; ++it) {
            if (ictl[0]) break;
            float lo = fctl[0], hi = fctl[1];
            float step = (hi - lo) * 0.2f;
            float t0 = lo + step, t1 = lo + 2.f*step, t2 = lo + 3.f*step, t3 = lo + 4.f*step;
            int c0 = 0, c1 = 0, c2 = 0, c3 = 0;
            for (int i = tid; i < VV; i += NT) {
                float x = lrow[i];
                c0 += (x >= t0); c1 += (x >= t1); c2 += (x >= t2); c3 += (x >= t3);
            }
            #pragma unroll
            for (int o = 16; o; o >>= 1) {
                c0 += __shfl_xor_sync(0xffffffffu, c0, o);
                c1 += __shfl_xor_sync(0xffffffffu, c1, o);
                c2 += __shfl_xor_sync(0xffffffffu, c2, o);
                c3 += __shfl_xor_sync(0xffffffffu, c3, o);
            }
            if (lane == 0) {
                atomicAdd(&icnt[0], c0); atomicAdd(&icnt[1], c1);
                atomicAdd(&icnt[2], c2); atomicAdd(&icnt[3], c3);
            }
            __syncthreads();
            if (tid == 0) {
                int   n[5]  = { ictl[1], icnt[0], icnt[1], icnt[2], icnt[3] };
                float tt[5] = { lo, t0, t1, t2, t3 };
                int j = 0;
                for (int q = 1; q < 5; ++q) if (n[q] >= KSEL) j = q;
                bool degen = !(t0 > lo && t3 < hi);
                if (n[j] <= BUFCAP || degen || it == 29) {
                    fctl[2] = tt[j]; ictl[0] = 1;
                } else {
                    fctl[0] = tt[j]; ictl[1] = n[j];
                    fctl[1] = (j < 4) ? tt[j + 1] : hi;
                }
                icnt[0] = icnt[1] = icnt[2] = icnt[3] = 0;
            }
            __syncthreads();
        }
        float T = fctl[2];
        if (tid == 0) qcnt = 0;
        __syncthreads();
        for (int i = tid; i < VV; i += NT) {
            float x = lrow[i];
            if (x >= T) {
                int p = atomicAdd(&qcnt, 1);
                if (p < BUFCAP) buf[p] = make_comp(x, (unsigned)i);
            }
        }
        __syncthreads();
        C = min(qcnt, BUFCAP);
    }
    __syncthreads();

    // ------------- counting-sort ranking -------------
    unsigned long long m0 = (tid      < C) ? buf[tid]      : 0ull;
    unsigned long long m1 = (tid + NT < C) ? buf[tid + NT] : 0ull;
    const unsigned k0 = (unsigned)(m0 >> 32);
    const unsigned k1 = (unsigned)(m1 >> 32);

    {
        unsigned kmn = 0xffffffffu, kmx = 0u;
        if (tid      < C) { kmn = min(kmn, k0); kmx = max(kmx, k0); }
        if (tid + NT < C) { kmn = min(kmn, k1); kmx = max(kmx, k1); }
        #pragma unroll
        for (int o = 16; o; o >>= 1) {
            kmn = min(kmn, __shfl_xor_sync(0xffffffffu, kmn, o));
            kmx = max(kmx, __shfl_xor_sync(0xffffffffu, kmx, o));
        }
        if (lane == 0) { atomicMin(&skmin, kmn); atomicMax(&skmax, kmx); }
    }
    __syncthreads();
    const unsigned kminv = skmin;
    const unsigned long long spanp1 = (unsigned long long)(skmax - skmin) + 1ull;

    int b0 = -1, b1 = -1;
    if (tid      < C) b0 = (int)(((unsigned long long)(k0 - kminv) * NB) / spanp1);
    if (tid + NT < C) b1 = (int)(((unsigned long long)(k1 - kminv) * NB) / spanp1);
    if (b0 >= 0) atomicAdd(&hist[b0], 1);
    if (b1 >= 0) atomicAdd(&hist[b1], 1);
    __syncthreads();

    // exclusive ascending scan of hist[NB] -> preA[NB], 2 bins/thread
    {
        const int bq = tid * 2;
        int h0 = hist[bq], h1 = hist[bq + 1];
        int s = h0 + h1;
        int incl = s;
        #pragma unroll
        for (int o = 1; o < 32; o <<= 1) {
            int n = __shfl_up_sync(0xffffffffu, incl, o);
            if (lane >= o) incl += n;
        }
        if (lane == 31) wsum[wid] = incl;
        __syncthreads();
        if (wid == 0) {
            int w = (lane < 8) ? wsum[lane] : 0;
            int wi = w;
            #pragma unroll
            for (int o = 1; o < 8; o <<= 1) {
                int n = __shfl_up_sync(0xffffffffu, wi, o);
                if (lane >= o) wi += n;
            }
            if (lane < 8) woff[lane] = wi - w;
        }
        __syncthreads();
        int run = incl - s + woff[wid];
        preA[bq]     = run;  run += h0;
        preA[bq + 1] = run;
    }
    __syncthreads();

    int st0 = 0, ln0 = 0, st1 = 0, ln1 = 0;
    if (b0 >= 0) { st0 = preA[b0]; ln0 = hist[b0]; }
    if (b1 >= 0) { st1 = preA[b1]; ln1 = hist[b1]; }
    __syncthreads();
    if (b0 >= 0) { int p = atomicAdd(&preA[b0], 1); bkt[p] = m0; }
    if (b1 >= 0) { int p = atomicAdd(&preA[b1], 1); bkt[p] = m1; }
    __syncthreads();

    int r0 = 0, r1 = 0;
    if (b0 >= 0) {
        r0 = C - (st0 + ln0);
        for (int j = st0; j < st0 + ln0; ++j) r0 += (bkt[j] > m0);
    }
    if (b1 >= 0) {
        r1 = C - (st1 + ln1);
        for (int j = st1; j < st1 + ln1; ++j) r1 += (bkt[j] > m1);
    }

    // ------------- fused dot + direct scatter -------------
    const float c0v = fctl[3];
    const float4* __restrict__ u4 = reinterpret_cast<const float4*>(su);
    #pragma unroll
    for (int s = 0; s < 2; ++s) {
        int b = s ? b1 : b0;
        int r = s ? r1 : r0;
        unsigned long long mine = s ? m1 : m0;
        if (b >= 0 && r < KSEL) {
            unsigned idx = ~((unsigned)(mine & 0xffffffffull));
            const float4* __restrict__ wr =
                reinterpret_cast<const float4*>(W + (size_t)idx * EE);
            float acc = 0.f, wsq = 0.f;
            #pragma unroll
            for (int q = 0; q < EE / 4; ++q) {
                float4 w = wr[q], u = u4[q];
                acc += w.x * u.x + w.y * u.y + w.z * u.z + w.w * u.w;
                wsq += w.x * w.x + w.y * w.y + w.z * w.z + w.w * w.w;
            }
            size_t o = (size_t)row * KSEL + (size_t)r;
            out[o] = acc - 10.0f * wsq + c0v;
            out[(size_t)NROWS * KSEL + o] = (float)idx;
        }
    }
}

// ---------------------------------------------------------------------------
// Fused kernel: stream quarter-row, last CTA of each row runs the selector.
// ---------------------------------------------------------------------------
__global__ void __launch_bounds__(NT, 8) fused_kernel(
    const float* __restrict__ gx, const float* __restrict__ cb,
    const float* __restrict__ W,  const float* __restrict__ logits,
    float* __restrict__ out)
{
    __shared__ int scnt;
    __shared__ int slast;

    const int tid   = threadIdx.x;
    const int chunk = blockIdx.x;
    const int row   = blockIdx.y;
    const float* __restrict__ lrow = logits + (size_t)row * VV;

    if (tid == 0) scnt = 0;
    __syncthreads();

    uintptr_t a = (uintptr_t)lrow;
    const int lead  = (int)(((16u - (unsigned)(a & 15u)) & 15u) >> 2);
    const int nv4   = (VV - lead) >> 2;
    const int tail0 = lead + nv4 * 4;
    const float4* __restrict__ l4 = reinterpret_cast<const float4*>(lrow + lead);
    unsigned long long* __restrict__ slot = g_cand + ((size_t)(row * CH + chunk)) * SLOT;

    const int c4 = (nv4 + CH - 1) / CH;
    const int b4 = chunk * c4;
    const int e4 = min(b4 + c4, nv4);

    if (chunk == 0) {
        for (int i = tid; i < lead; i += NT) {
            float x = __ldcs(&lrow[i]);
            if (x >= T0) {
                int p = atomicAdd(&scnt, 1);
                if (p < SLOT) slot[p] = make_comp(x, (unsigned)i);
            }
        }
    }
    if (chunk == CH - 1) {
        for (int i = tail0 + tid; i < VV; i += NT) {
            float x = __ldcs(&lrow[i]);
            if (x >= T0) {
                int p = atomicAdd(&scnt, 1);
                if (p < SLOT) slot[p] = make_comp(x, (unsigned)i);
            }
        }
    }
    #pragma unroll 4
    for (int i = b4 + tid; i < e4; i += NT) {
        float4 x = __ldcs(&l4[i]);
        unsigned pr = (x.x >= T0 ? 1u : 0u) | (x.y >= T0 ? 2u : 0u)
                    | (x.z >= T0 ? 4u : 0u) | (x.w >= T0 ? 8u : 0u);
        if (pr) {
            int base = atomicAdd(&scnt, __popc(pr));
            float vals[4] = { x.x, x.y, x.z, x.w };
            unsigned g0 = (unsigned)(lead + 4 * i);
            #pragma unroll
            for (int c = 0; c < 4; ++c) {
                if (pr & (1u << c)) {
                    if (base < SLOT) slot[base] = make_comp(vals[c], g0 + c);
                    ++base;
                }
            }
        }
    }
    __syncthreads();
    if (tid == 0) g_cnt[row * CH + chunk] = scnt;
    __threadfence();             // release: slot + g_cnt visible before ticket
    __syncthreads();
    if (tid == 0) {
        int old = atomicAdd(&g_done[row], 1);
        slast = (old == CH - 1);
    }
    __syncthreads();
    if (!slast) return;
    __threadfence();             // acquire: other CTAs' slot/g_cnt now visible
    if (tid == 0) g_done[row] = 0;   // reset for next launch/replay

    selector(row, gx, cb, W, logits, out);
}

extern "C" void kernel_launch(void* const* d_in, const int* in_sizes, int n_in,
                              void* d_out, int out_size)
{
    (void)in_sizes; (void)n_in; (void)out_size;
    fused_kernel<<<dim3(CH, NROWS), NT>>>(
        (const float*)d_in[0], (const float*)d_in[1],
        (const float*)d_in[2], (const float*)d_in[3], (float*)d_out);
}